// round 1
// baseline (speedup 1.0000x reference)
#include <cuda_runtime.h>
#include <math.h>

#define E_DIM 1024
#define H_NUM 16
#define D_DIM 64
#define B_NUM 4
#define S_LEN 1024
#define F_DIM 4096
#define M_ROWS (B_NUM * S_LEN)  // 4096

// ---------------- scratch (static device globals; no runtime allocation) ----
__device__ float g_h[M_ROWS * E_DIM];
__device__ float g_q[M_ROWS * E_DIM];
__device__ float g_k[M_ROWS * E_DIM];
__device__ float g_v[M_ROWS * E_DIM];
__device__ float g_att[M_ROWS * E_DIM];
__device__ float g_x1[M_ROWS * E_DIM];
__device__ float g_x2[M_ROWS * E_DIM];
__device__ float g_ff[(size_t)M_ROWS * F_DIM];     // 64 MB
__device__ float g_Wr[6 * E_DIM * E_DIM];          // repacked Wq1,Wk1,Wv1,Wq2,Wk2,Wv2

// ---------------- weight repack: [H,E,D] -> [E, H*D] row-major --------------
__global__ void repack_kernel(const float* __restrict__ src, float* __restrict__ dst) {
    int idx = blockIdx.x * 256 + threadIdx.x;     // idx = e*1024 + n
    int e = idx >> 10;
    int n = idx & 1023;
    int h = n >> 6;
    int d = n & 63;
    dst[idx] = src[h * (E_DIM * D_DIM) + e * D_DIM + d];
}

// ---------------- LayerNorm: one block per row (E=1024, 256 thr x float4) ---
__global__ void __launch_bounds__(256) ln_kernel(const float* __restrict__ x,
                                                 const float* __restrict__ g,
                                                 const float* __restrict__ b,
                                                 float* __restrict__ out) {
    int row = blockIdx.x;
    int t = threadIdx.x;
    const float4* xr = (const float4*)(x + (size_t)row * E_DIM);
    float4 v = xr[t];
    float s = v.x + v.y + v.z + v.w;
    float ss = v.x * v.x + v.y * v.y + v.z * v.z + v.w * v.w;
    #pragma unroll
    for (int o = 16; o > 0; o >>= 1) {
        s  += __shfl_xor_sync(0xffffffffu, s, o);
        ss += __shfl_xor_sync(0xffffffffu, ss, o);
    }
    __shared__ float red[2][8];
    int w = t >> 5, lane = t & 31;
    if (lane == 0) { red[0][w] = s; red[1][w] = ss; }
    __syncthreads();
    s = 0.0f; ss = 0.0f;
    #pragma unroll
    for (int i = 0; i < 8; i++) { s += red[0][i]; ss += red[1][i]; }
    float mu  = s * (1.0f / E_DIM);
    float var = ss * (1.0f / E_DIM) - mu * mu;
    float inv = rsqrtf(var + 1e-5f);
    float4 gv = ((const float4*)g)[t];
    float4 bv = ((const float4*)b)[t];
    float4 o4;
    o4.x = (v.x - mu) * inv * gv.x + bv.x;
    o4.y = (v.y - mu) * inv * gv.y + bv.y;
    o4.z = (v.z - mu) * inv * gv.z + bv.z;
    o4.w = (v.w - mu) * inv * gv.w + bv.w;
    ((float4*)(out + (size_t)row * E_DIM))[t] = o4;
}

// ---------------- SGEMM: C[M,N] = epi(A[M,K] @ W[K,N] + bias) ---------------
// EPI: 0 = bias only, 1 = bias + exact GELU, 2 = bias + residual add
// 128x128 tile, K-step 8, 256 threads, 8x8 per-thread microtile.
// Requires M,N % 128 == 0 and K % 8 == 0 (true for all uses here).
template <int EPI>
__global__ void __launch_bounds__(256) sgemm_kernel(
    const float* __restrict__ A, const float* __restrict__ W,
    const float* __restrict__ bias, const float* __restrict__ res,
    float* __restrict__ C, int M, int N, int K) {
    __shared__ float As[8][128];
    __shared__ float Bs[8][128];
    int tid = threadIdx.x;
    int cBase = blockIdx.x * 128;
    int rBase = blockIdx.y * 128;
    int ty = tid >> 4;        // 0..15
    int tx = tid & 15;        // 0..15

    float acc[8][8];
    #pragma unroll
    for (int i = 0; i < 8; i++)
        #pragma unroll
        for (int j = 0; j < 8; j++) acc[i][j] = 0.0f;

    int arow = tid >> 1;             // 0..127
    int ak   = (tid & 1) << 2;       // 0 or 4
    int bk   = tid >> 5;             // 0..7
    int bn   = (tid & 31) << 2;      // 0..124
    const float* Aptr = A + (size_t)(rBase + arow) * K + ak;
    const float* Wptr = W + (size_t)bk * N + cBase + bn;

    for (int k0 = 0; k0 < K; k0 += 8) {
        float4 av = *(const float4*)(Aptr + k0);
        float4 bv = *(const float4*)(Wptr + (size_t)k0 * N);
        __syncthreads();
        As[ak + 0][arow] = av.x;
        As[ak + 1][arow] = av.y;
        As[ak + 2][arow] = av.z;
        As[ak + 3][arow] = av.w;
        *(float4*)&Bs[bk][bn] = bv;
        __syncthreads();
        #pragma unroll
        for (int kk = 0; kk < 8; kk++) {
            float a0[8], b0[8];
            *(float4*)&a0[0] = *(const float4*)&As[kk][ty * 8];
            *(float4*)&a0[4] = *(const float4*)&As[kk][ty * 8 + 4];
            *(float4*)&b0[0] = *(const float4*)&Bs[kk][tx * 8];
            *(float4*)&b0[4] = *(const float4*)&Bs[kk][tx * 8 + 4];
            #pragma unroll
            for (int i = 0; i < 8; i++)
                #pragma unroll
                for (int j = 0; j < 8; j++)
                    acc[i][j] += a0[i] * b0[j];
        }
    }

    #pragma unroll
    for (int i = 0; i < 8; i++) {
        int row = rBase + ty * 8 + i;
        #pragma unroll
        for (int j = 0; j < 8; j += 4) {
            int col = cBase + tx * 8 + j;
            float4 o;
            float* po = &o.x;
            #pragma unroll
            for (int u = 0; u < 4; u++) {
                float vv = acc[i][j + u] + bias[col + u];
                if (EPI == 1) vv = 0.5f * vv * (1.0f + erff(vv * 0.70710678118654752f));
                if (EPI == 2) vv += res[(size_t)row * N + col + u];
                po[u] = vv;
            }
            *(float4*)(C + (size_t)row * N + col) = o;
        }
    }
}

// ---------------- Flash attention (fp32, no 1/sqrt(d), D=64) ---------------
// grid (S/64, H, B), 256 threads. Q/K/V/O layout: [B,S,H,D].
// Per block: 64 queries. Scores & PV: 4x4 per-thread microtiles.
// Shared: Qs [d][q], KP reused as K^T [d][k] then P [k][swz(q)], Vs [k][d].
template <bool CAUSAL>
__global__ void __launch_bounds__(256) attn_kernel(
    const float* __restrict__ Q, const float* __restrict__ K,
    const float* __restrict__ V, float* __restrict__ O) {
    __shared__ float Qs[64 * 64];
    __shared__ float KP[64 * 64];
    __shared__ float Vs[64 * 64];
    int b  = blockIdx.z;
    int hh = blockIdx.y;
    int qt = blockIdx.x;
    int tid = threadIdx.x;
    int qy = tid >> 4;   // 0..15 -> queries qy*4..qy*4+3
    int tx = tid & 15;   // 0..15 -> keys/dims tx*4..tx*4+3

    // Load Q tile transposed: Qs[d*64 + q]
    {
        int qq = tid & 63;
        int dc = (tid >> 6) << 4;
        const float* src = Q + ((size_t)((b * S_LEN + qt * 64 + qq) * H_NUM + hh)) * D_DIM + dc;
        #pragma unroll
        for (int i = 0; i < 16; i += 4) {
            float4 vv = *(const float4*)(src + i);
            Qs[(dc + i + 0) * 64 + qq] = vv.x;
            Qs[(dc + i + 1) * 64 + qq] = vv.y;
            Qs[(dc + i + 2) * 64 + qq] = vv.z;
            Qs[(dc + i + 3) * 64 + qq] = vv.w;
        }
    }

    float o[4][4];
    float m[4], l[4];
    #pragma unroll
    for (int i = 0; i < 4; i++) {
        m[i] = -1e30f;
        l[i] = 0.0f;
        #pragma unroll
        for (int j = 0; j < 4; j++) o[i][j] = 0.0f;
    }

    int ntiles = CAUSAL ? (qt + 1) : (S_LEN / 64);
    for (int kt = 0; kt < ntiles; kt++) {
        __syncthreads();  // protects KP (prev P) & Vs until PV done; Q ready on iter 0
        // Load K tile transposed into KP, V tile natural into Vs
        {
            int kk = tid & 63;
            int dc = (tid >> 6) << 4;
            const float* ks = K + ((size_t)((b * S_LEN + kt * 64 + kk) * H_NUM + hh)) * D_DIM + dc;
            #pragma unroll
            for (int i = 0; i < 16; i += 4) {
                float4 vv = *(const float4*)(ks + i);
                KP[(dc + i + 0) * 64 + kk] = vv.x;
                KP[(dc + i + 1) * 64 + kk] = vv.y;
                KP[(dc + i + 2) * 64 + kk] = vv.z;
                KP[(dc + i + 3) * 64 + kk] = vv.w;
            }
            int kv = tid >> 2;
            int d4 = (tid & 3) << 4;
            const float* vsp = V + ((size_t)((b * S_LEN + kt * 64 + kv) * H_NUM + hh)) * D_DIM + d4;
            #pragma unroll
            for (int i = 0; i < 16; i += 4)
                *(float4*)&Vs[kv * 64 + d4 + i] = *(const float4*)(vsp + i);
        }
        __syncthreads();

        // Scores: s[4q][4k] = sum_d Q^T * K^T
        float s[4][4];
        #pragma unroll
        for (int i = 0; i < 4; i++)
            #pragma unroll
            for (int j = 0; j < 4; j++) s[i][j] = 0.0f;
        #pragma unroll 8
        for (int d = 0; d < 64; d++) {
            float4 a  = *(const float4*)&Qs[d * 64 + (qy << 2)];
            float4 bb = *(const float4*)&KP[d * 64 + (tx << 2)];
            float av[4] = {a.x, a.y, a.z, a.w};
            float bv[4] = {bb.x, bb.y, bb.z, bb.w};
            #pragma unroll
            for (int i = 0; i < 4; i++)
                #pragma unroll
                for (int j = 0; j < 4; j++)
                    s[i][j] += av[i] * bv[j];
        }

        if (CAUSAL && kt == qt) {
            #pragma unroll
            for (int i = 0; i < 4; i++)
                #pragma unroll
                for (int j = 0; j < 4; j++)
                    if ((tx << 2) + j > (qy << 2) + i) s[i][j] = -1e30f;
        }

        // Online softmax bookkeeping (rows of 64 keys split across 16 tx lanes)
        #pragma unroll
        for (int i = 0; i < 4; i++) {
            float mt = fmaxf(fmaxf(s[i][0], s[i][1]), fmaxf(s[i][2], s[i][3]));
            #pragma unroll
            for (int off = 1; off < 16; off <<= 1)
                mt = fmaxf(mt, __shfl_xor_sync(0xffffffffu, mt, off));
            float mn = fmaxf(m[i], mt);
            float sc = __expf(m[i] - mn);
            float ts = 0.0f;
            #pragma unroll
            for (int j = 0; j < 4; j++) {
                s[i][j] = __expf(s[i][j] - mn);
                ts += s[i][j];
            }
            #pragma unroll
            for (int off = 1; off < 16; off <<= 1)
                ts += __shfl_xor_sync(0xffffffffu, ts, off);
            l[i] = l[i] * sc + ts;
            m[i] = mn;
            #pragma unroll
            for (int j = 0; j < 4; j++) o[i][j] *= sc;
        }

        __syncthreads();  // done reading K^T from KP
        // Write P transposed with XOR swizzle: KP[k*64 + ((qy ^ (k&15))<<2)] = p[q0..3][k]
        #pragma unroll
        for (int kj = 0; kj < 4; kj++) {
            int kkk = (tx << 2) + kj;
            int col = ((qy ^ (kkk & 15)) << 2);
            *(float4*)&KP[kkk * 64 + col] = make_float4(s[0][kj], s[1][kj], s[2][kj], s[3][kj]);
        }
        __syncthreads();

        // PV: o[4q][4d] += sum_k P[q][k] * V[k][d]
        #pragma unroll 8
        for (int kkk = 0; kkk < 64; kkk++) {
            float4 a  = *(const float4*)&KP[kkk * 64 + ((qy ^ (kkk & 15)) << 2)];
            float4 bb = *(const float4*)&Vs[kkk * 64 + (tx << 2)];
            float av[4] = {a.x, a.y, a.z, a.w};
            float bv[4] = {bb.x, bb.y, bb.z, bb.w};
            #pragma unroll
            for (int i = 0; i < 4; i++)
                #pragma unroll
                for (int j = 0; j < 4; j++)
                    o[i][j] += av[i] * bv[j];
        }
    }

    // Epilogue: O = o / l
    #pragma unroll
    for (int i = 0; i < 4; i++) {
        float inv = 1.0f / l[i];
        int qq = qt * 64 + (qy << 2) + i;
        float4 ov = make_float4(o[i][0] * inv, o[i][1] * inv, o[i][2] * inv, o[i][3] * inv);
        *(float4*)(O + ((size_t)((b * S_LEN + qq) * H_NUM + hh)) * D_DIM + (tx << 2)) = ov;
    }
}

// ---------------- launch --------------------------------------------------
extern "C" void kernel_launch(void* const* d_in, const int* in_sizes, int n_in,
                              void* d_out, int out_size) {
    const float* x    = (const float*)d_in[0];
    const float* enc  = (const float*)d_in[1];
    const float* ln1g = (const float*)d_in[2];
    const float* ln1b = (const float*)d_in[3];
    const float* ln2g = (const float*)d_in[4];
    const float* ln2b = (const float*)d_in[5];
    const float* ln3g = (const float*)d_in[6];
    const float* ln3b = (const float*)d_in[7];
    const float* Wq1  = (const float*)d_in[8];
    const float* bq1  = (const float*)d_in[9];
    const float* Wk1  = (const float*)d_in[10];
    const float* bk1  = (const float*)d_in[11];
    const float* Wv1  = (const float*)d_in[12];
    const float* bv1  = (const float*)d_in[13];
    const float* Wo1  = (const float*)d_in[14];
    const float* bo1  = (const float*)d_in[15];
    const float* Wq2  = (const float*)d_in[16];
    const float* bq2  = (const float*)d_in[17];
    const float* Wk2  = (const float*)d_in[18];
    const float* bk2  = (const float*)d_in[19];
    const float* Wv2  = (const float*)d_in[20];
    const float* bv2  = (const float*)d_in[21];
    const float* Wo2  = (const float*)d_in[22];
    const float* bo2  = (const float*)d_in[23];
    const float* Wup  = (const float*)d_in[24];
    const float* bup  = (const float*)d_in[25];
    const float* Wdn  = (const float*)d_in[26];
    const float* bdn  = (const float*)d_in[27];
    float* out = (float*)d_out;

    float *h, *q, *k, *v, *att, *x1, *x2, *ff, *Wr;
    cudaGetSymbolAddress((void**)&h,   g_h);
    cudaGetSymbolAddress((void**)&q,   g_q);
    cudaGetSymbolAddress((void**)&k,   g_k);
    cudaGetSymbolAddress((void**)&v,   g_v);
    cudaGetSymbolAddress((void**)&att, g_att);
    cudaGetSymbolAddress((void**)&x1,  g_x1);
    cudaGetSymbolAddress((void**)&x2,  g_x2);
    cudaGetSymbolAddress((void**)&ff,  g_ff);
    cudaGetSymbolAddress((void**)&Wr,  g_Wr);

    const int WSTRIDE = E_DIM * E_DIM;  // 1048576
    dim3 gSq(E_DIM / 128, M_ROWS / 128);   // (8, 32)
    dim3 gUp(F_DIM / 128, M_ROWS / 128);   // (32, 32)
    dim3 gAttn(S_LEN / 64, H_NUM, B_NUM);  // (16, 16, 4)

    // Repack per-head projection weights to [E, H*D]
    repack_kernel<<<4096, 256>>>(Wq1, Wr + 0 * WSTRIDE);
    repack_kernel<<<4096, 256>>>(Wk1, Wr + 1 * WSTRIDE);
    repack_kernel<<<4096, 256>>>(Wv1, Wr + 2 * WSTRIDE);
    repack_kernel<<<4096, 256>>>(Wq2, Wr + 3 * WSTRIDE);
    repack_kernel<<<4096, 256>>>(Wk2, Wr + 4 * WSTRIDE);
    repack_kernel<<<4096, 256>>>(Wv2, Wr + 5 * WSTRIDE);

    // Block 1: causal self-attention
    ln_kernel<<<M_ROWS, 256>>>(x, ln1g, ln1b, h);
    sgemm_kernel<0><<<gSq, 256>>>(h, Wr + 0 * WSTRIDE, bq1, nullptr, q, M_ROWS, E_DIM, E_DIM);
    sgemm_kernel<0><<<gSq, 256>>>(h, Wr + 1 * WSTRIDE, bk1, nullptr, k, M_ROWS, E_DIM, E_DIM);
    sgemm_kernel<0><<<gSq, 256>>>(h, Wr + 2 * WSTRIDE, bv1, nullptr, v, M_ROWS, E_DIM, E_DIM);
    attn_kernel<true><<<gAttn, 256>>>(q, k, v, att);
    sgemm_kernel<2><<<gSq, 256>>>(att, Wo1, bo1, x, x1, M_ROWS, E_DIM, E_DIM);

    // Block 2: cross-attention with enc
    ln_kernel<<<M_ROWS, 256>>>(x1, ln2g, ln2b, h);
    sgemm_kernel<0><<<gSq, 256>>>(h,   Wr + 3 * WSTRIDE, bq2, nullptr, q, M_ROWS, E_DIM, E_DIM);
    sgemm_kernel<0><<<gSq, 256>>>(enc, Wr + 4 * WSTRIDE, bk2, nullptr, k, M_ROWS, E_DIM, E_DIM);
    sgemm_kernel<0><<<gSq, 256>>>(enc, Wr + 5 * WSTRIDE, bv2, nullptr, v, M_ROWS, E_DIM, E_DIM);
    attn_kernel<false><<<gAttn, 256>>>(q, k, v, att);
    sgemm_kernel<2><<<gSq, 256>>>(att, Wo2, bo2, x1, x2, M_ROWS, E_DIM, E_DIM);

    // FFN
    ln_kernel<<<M_ROWS, 256>>>(x2, ln3g, ln3b, h);
    sgemm_kernel<1><<<gUp, 256>>>(h, Wup, bup, nullptr, ff, M_ROWS, F_DIM, E_DIM);
    sgemm_kernel<2><<<gSq, 256>>>(ff, Wdn, bdn, x2, out, M_ROWS, E_DIM, F_DIM);
}

// round 3
// speedup vs baseline: 1.8747x; 1.8747x over previous
#include <cuda_runtime.h>
#include <cuda_bf16.h>
#include <math.h>
#include <cstdint>

#define E_DIM 1024
#define H_NUM 16
#define D_DIM 64
#define B_NUM 4
#define S_LEN 1024
#define F_DIM 4096
#define M_ROWS (B_NUM * S_LEN)  // 4096
#define MB1 (1024 * 1024)

// ---------------- scratch (static device globals) ---------------------------
__device__ __align__(16) __nv_bfloat16 g_Bh[16 * MB1];   // transposed/split weights hi
__device__ __align__(16) __nv_bfloat16 g_Bl[16 * MB1];   // transposed/split weights lo
__device__ __align__(16) __nv_bfloat16 g_hh[4 * MB1], g_hl[4 * MB1];    // LN out
__device__ __align__(16) __nv_bfloat16 g_ath[4 * MB1], g_atl[4 * MB1];  // attn out
__device__ __align__(16) __nv_bfloat16 g_ech[4 * MB1], g_ecl[4 * MB1];  // enc split
__device__ __align__(16) __nv_bfloat16 g_ffh[16 * MB1], g_ffl[16 * MB1];
__device__ __align__(16) float g_q[4 * MB1], g_k[4 * MB1], g_v[4 * MB1];
__device__ __align__(16) float g_x1[4 * MB1], g_x2[4 * MB1];

// ---------------- PTX helpers -----------------------------------------------
__device__ __forceinline__ uint32_t smem_u32(const void* p) {
    uint32_t a;
    asm("{ .reg .u64 t; cvta.to.shared.u64 t, %1; cvt.u32.u64 %0, t; }" : "=r"(a) : "l"(p));
    return a;
}
__device__ __forceinline__ void cpasync16(uint32_t dst, const void* src) {
    asm volatile("cp.async.cg.shared.global [%0], [%1], 16;" :: "r"(dst), "l"(src));
}
__device__ __forceinline__ void cpcommit() { asm volatile("cp.async.commit_group;" ::: "memory"); }
template <int N>
__device__ __forceinline__ void cpwait() { asm volatile("cp.async.wait_group %0;" :: "n"(N) : "memory"); }

__device__ __forceinline__ void ldsm4(uint32_t (&r)[4], uint32_t addr) {
    asm volatile("ldmatrix.sync.aligned.m8n8.x4.shared.b16 {%0,%1,%2,%3}, [%4];"
                 : "=r"(r[0]), "=r"(r[1]), "=r"(r[2]), "=r"(r[3]) : "r"(addr));
}
__device__ __forceinline__ void ldsm2(uint32_t (&r)[2], uint32_t addr) {
    asm volatile("ldmatrix.sync.aligned.m8n8.x2.shared.b16 {%0,%1}, [%2];"
                 : "=r"(r[0]), "=r"(r[1]) : "r"(addr));
}
__device__ __forceinline__ void mma16816(float (&d)[4], const uint32_t (&a)[4],
                                         const uint32_t (&b)[2]) {
    asm volatile(
        "mma.sync.aligned.m16n8k16.row.col.f32.bf16.bf16.f32 "
        "{%0,%1,%2,%3}, {%4,%5,%6,%7}, {%8,%9}, {%0,%1,%2,%3};"
        : "+f"(d[0]), "+f"(d[1]), "+f"(d[2]), "+f"(d[3])
        : "r"(a[0]), "r"(a[1]), "r"(a[2]), "r"(a[3]), "r"(b[0]), "r"(b[1]));
}

__device__ __forceinline__ void bf_split(float v, __nv_bfloat16& hi, __nv_bfloat16& lo) {
    hi = __float2bfloat16_rn(v);
    lo = __float2bfloat16_rn(v - __bfloat162float(hi));
}

// ---------------- weight prep kernels ---------------------------------------
// [H,E,D] -> Bt[n=h*64+d][k=e]
__global__ void wqkv_split(const float* __restrict__ src,
                           __nv_bfloat16* __restrict__ oh, __nv_bfloat16* __restrict__ ol) {
    int idx = blockIdx.x * 256 + threadIdx.x;  // over 1M
    int n = idx >> 10, k = idx & 1023;
    int h = n >> 6, d = n & 63;
    float v = src[h * (E_DIM * D_DIM) + k * D_DIM + d];
    __nv_bfloat16 hi, lo; bf_split(v, hi, lo);
    oh[idx] = hi; ol[idx] = lo;
}
// [K,N] row-major -> Bt[n][k]
__global__ void wt_split(const float* __restrict__ src,
                         __nv_bfloat16* __restrict__ oh, __nv_bfloat16* __restrict__ ol,
                         int K, int N) {
    __shared__ float tile[32][33];
    int n0 = blockIdx.x * 32, k0 = blockIdx.y * 32;
    int tx = threadIdx.x, ty = threadIdx.y;  // (32,8)
    #pragma unroll
    for (int i = 0; i < 4; i++)
        tile[ty + 8 * i][tx] = src[(size_t)(k0 + ty + 8 * i) * N + n0 + tx];
    __syncthreads();
    #pragma unroll
    for (int i = 0; i < 4; i++) {
        float v = tile[tx][ty + 8 * i];
        __nv_bfloat16 hi, lo; bf_split(v, hi, lo);
        size_t oidx = (size_t)(n0 + ty + 8 * i) * K + k0 + tx;
        oh[oidx] = hi; ol[oidx] = lo;
    }
}
// f32 -> hi/lo bf16 (vectorized, n/4 threads)
__global__ void split4(const float* __restrict__ src,
                       __nv_bfloat16* __restrict__ oh, __nv_bfloat16* __restrict__ ol) {
    int i = blockIdx.x * 256 + threadIdx.x;
    float4 v = ((const float4*)src)[i];
    __nv_bfloat16 h0, h1, h2, h3, l0, l1, l2, l3;
    bf_split(v.x, h0, l0); bf_split(v.y, h1, l1);
    bf_split(v.z, h2, l2); bf_split(v.w, h3, l3);
    __nv_bfloat162 a, b;
    a.x = h0; a.y = h1; b.x = h2; b.y = h3;
    *(__nv_bfloat162*)(oh + 4 * (size_t)i) = a;
    *(__nv_bfloat162*)(oh + 4 * (size_t)i + 2) = b;
    a.x = l0; a.y = l1; b.x = l2; b.y = l3;
    *(__nv_bfloat162*)(ol + 4 * (size_t)i) = a;
    *(__nv_bfloat162*)(ol + 4 * (size_t)i + 2) = b;
}

// ---------------- LayerNorm: f32 in -> bf16 hi/lo out ------------------------
__global__ void __launch_bounds__(256) ln_kernel(const float* __restrict__ x,
                                                 const float* __restrict__ g,
                                                 const float* __restrict__ b,
                                                 __nv_bfloat16* __restrict__ oh,
                                                 __nv_bfloat16* __restrict__ ol) {
    int row = blockIdx.x;
    int t = threadIdx.x;
    float4 v = ((const float4*)(x + (size_t)row * E_DIM))[t];
    float s = v.x + v.y + v.z + v.w;
    float ss = v.x * v.x + v.y * v.y + v.z * v.z + v.w * v.w;
    #pragma unroll
    for (int o = 16; o > 0; o >>= 1) {
        s  += __shfl_xor_sync(0xffffffffu, s, o);
        ss += __shfl_xor_sync(0xffffffffu, ss, o);
    }
    __shared__ float red[2][8];
    int w = t >> 5, lane = t & 31;
    if (lane == 0) { red[0][w] = s; red[1][w] = ss; }
    __syncthreads();
    s = 0.0f; ss = 0.0f;
    #pragma unroll
    for (int i = 0; i < 8; i++) { s += red[0][i]; ss += red[1][i]; }
    float mu  = s * (1.0f / E_DIM);
    float var = ss * (1.0f / E_DIM) - mu * mu;
    float inv = rsqrtf(var + 1e-5f);
    float4 gv = ((const float4*)g)[t];
    float4 bv = ((const float4*)b)[t];
    float o0 = (v.x - mu) * inv * gv.x + bv.x;
    float o1 = (v.y - mu) * inv * gv.y + bv.y;
    float o2 = (v.z - mu) * inv * gv.z + bv.z;
    float o3 = (v.w - mu) * inv * gv.w + bv.w;
    __nv_bfloat16 h0, h1, h2, h3, l0, l1, l2, l3;
    bf_split(o0, h0, l0); bf_split(o1, h1, l1);
    bf_split(o2, h2, l2); bf_split(o3, h3, l3);
    size_t base = (size_t)row * E_DIM + t * 4;
    __nv_bfloat162 a, bb;
    a.x = h0; a.y = h1; bb.x = h2; bb.y = h3;
    *(__nv_bfloat162*)(oh + base) = a; *(__nv_bfloat162*)(oh + base + 2) = bb;
    a.x = l0; a.y = l1; bb.x = l2; bb.y = l3;
    *(__nv_bfloat162*)(ol + base) = a; *(__nv_bfloat162*)(ol + base + 2) = bb;
}

// ---------------- HMMA bf16x3 GEMM -------------------------------------------
// C[M,N] = epi(Ah@Bh^T + Ah@Bl^T + Al@Bh^T + bias)
// A: [M,K] bf16 hi/lo row-major; B: [N,K] bf16 hi/lo row-major.
// CTA tile 128x128, BK=32, 4 warps (2x2), warp tile 64x64, double-buffered cp.async.
// SMEM stage layout: Ah[2kc][128m][16] @0, Al @8K, Bh @16K, Bl @24K; XOR-16 swizzle.
// EPI: 0 bias->f32, 1 bias+GELU->bf16 hi/lo, 2 bias+res->f32.
#define STAGE_BYTES 32768
#define GEMM_SMEM (2 * STAGE_BYTES + 256)
template <int EPI>
__global__ void __launch_bounds__(128, 2) gemm_hmma(
    const __nv_bfloat16* __restrict__ Ah, const __nv_bfloat16* __restrict__ Al,
    const __nv_bfloat16* __restrict__ Bh, const __nv_bfloat16* __restrict__ Bl,
    const float* __restrict__ bias, const float* __restrict__ res,
    float* __restrict__ outF, __nv_bfloat16* __restrict__ outH, __nv_bfloat16* __restrict__ outL,
    int M, int N, int K) {
    extern __shared__ char dyn[];
    uint32_t sb = (smem_u32(dyn) + 127) & ~127u;
    int tid = threadIdx.x, lane = tid & 31, wid = tid >> 5;
    int rBase = blockIdx.y * 128, cBase = blockIdx.x * 128;
    int m0 = (wid >> 1) * 64, n0 = (wid & 1) * 64;

    float acc[4][8][4];
    #pragma unroll
    for (int i = 0; i < 4; i++)
        #pragma unroll
        for (int j = 0; j < 8; j++)
            #pragma unroll
            for (int u = 0; u < 4; u++) acc[i][j][u] = 0.0f;

    const int nc = K >> 5;
    auto loadStage = [&](int s, int c) {
        uint32_t base = sb + s * STAGE_BYTES;
        int k0 = c << 5;
        #pragma unroll
        for (int i = 0; i < 4; i++) {
            int idx = i * 128 + tid;
            int row = idx >> 2, seg = idx & 3;
            uint32_t off = (seg >> 1) * 4096 + (((row * 32) + (seg & 1) * 16) ^ ((row & 4) << 2));
            size_t ga = (size_t)(rBase + row) * K + k0 + seg * 8;
            size_t gb = (size_t)(cBase + row) * K + k0 + seg * 8;
            cpasync16(base + off,         Ah + ga);
            cpasync16(base + 8192 + off,  Al + ga);
            cpasync16(base + 16384 + off, Bh + gb);
            cpasync16(base + 24576 + off, Bl + gb);
        }
    };

    // per-lane ldmatrix row/half components
    int aRow = (lane & 7) + ((lane >> 3) & 1) * 8;  // within 16-row frag
    int aH   = lane >> 4;
    int bRow = lane & 7;                             // within 8-row frag
    int bH   = (lane >> 3) & 1;

    loadStage(0, 0); cpcommit();

    for (int c = 0; c < nc; c++) {
        if (c + 1 < nc) { loadStage((c + 1) & 1, c + 1); cpcommit(); cpwait<1>(); }
        else            { cpwait<0>(); }
        __syncthreads();
        uint32_t base = sb + (c & 1) * STAGE_BYTES;
        #pragma unroll
        for (int kc = 0; kc < 2; kc++) {
            uint32_t bh[8][2], bl[8][2];
            #pragma unroll
            for (int j = 0; j < 8; j++) {
                int row = n0 + j * 8 + bRow;
                uint32_t off = kc * 4096 + (((row * 32) + bH * 16) ^ ((row & 4) << 2));
                ldsm2(bh[j], base + 16384 + off);
                ldsm2(bl[j], base + 24576 + off);
            }
            #pragma unroll
            for (int i = 0; i < 4; i++) {
                uint32_t ah[4], al[4];
                int row = m0 + i * 16 + aRow;
                uint32_t off = kc * 4096 + (((row * 32) + aH * 16) ^ ((row & 4) << 2));
                ldsm4(ah, base + off);
                ldsm4(al, base + 8192 + off);
                #pragma unroll
                for (int j = 0; j < 8; j++) {
                    mma16816(acc[i][j], ah, bh[j]);
                    mma16816(acc[i][j], ah, bl[j]);
                    mma16816(acc[i][j], al, bh[j]);
                }
            }
        }
        __syncthreads();
    }

    // Epilogue
    int lr = lane >> 2, lc = (lane & 3) << 1;
    #pragma unroll
    for (int i = 0; i < 4; i++) {
        #pragma unroll
        for (int half = 0; half < 2; half++) {
            size_t row = (size_t)(rBase + m0 + i * 16 + lr + half * 8);
            #pragma unroll
            for (int j = 0; j < 8; j++) {
                int col = cBase + n0 + j * 8 + lc;
                float v0 = acc[i][j][half * 2 + 0] + bias[col];
                float v1 = acc[i][j][half * 2 + 1] + bias[col + 1];
                if (EPI == 1) {
                    v0 = 0.5f * v0 * (1.0f + erff(v0 * 0.70710678118654752f));
                    v1 = 0.5f * v1 * (1.0f + erff(v1 * 0.70710678118654752f));
                    __nv_bfloat16 h0, h1, l0, l1;
                    bf_split(v0, h0, l0); bf_split(v1, h1, l1);
                    __nv_bfloat162 hp, lp;
                    hp.x = h0; hp.y = h1; lp.x = l0; lp.y = l1;
                    *(__nv_bfloat162*)(outH + row * N + col) = hp;
                    *(__nv_bfloat162*)(outL + row * N + col) = lp;
                } else {
                    if (EPI == 2) {
                        float2 rv = *(const float2*)(res + row * N + col);
                        v0 += rv.x; v1 += rv.y;
                    }
                    float2 o; o.x = v0; o.y = v1;
                    *(float2*)(outF + row * N + col) = o;
                }
            }
        }
    }
}

// ---------------- Flash attention (fp32, D=64) -> bf16 hi/lo out -------------
template <bool CAUSAL>
__global__ void __launch_bounds__(256) attn_kernel(
    const float* __restrict__ Q, const float* __restrict__ K,
    const float* __restrict__ V,
    __nv_bfloat16* __restrict__ Oh, __nv_bfloat16* __restrict__ Ol) {
    __shared__ float Qs[64 * 64];
    __shared__ float KP[64 * 64];
    __shared__ float Vs[64 * 64];
    int b  = blockIdx.z;
    int hh = blockIdx.y;
    int qt = blockIdx.x;
    int tid = threadIdx.x;
    int qy = tid >> 4;
    int tx = tid & 15;

    {
        int qq = tid & 63;
        int dc = (tid >> 6) << 4;
        const float* src = Q + ((size_t)((b * S_LEN + qt * 64 + qq) * H_NUM + hh)) * D_DIM + dc;
        #pragma unroll
        for (int i = 0; i < 16; i += 4) {
            float4 vv = *(const float4*)(src + i);
            Qs[(dc + i + 0) * 64 + qq] = vv.x;
            Qs[(dc + i + 1) * 64 + qq] = vv.y;
            Qs[(dc + i + 2) * 64 + qq] = vv.z;
            Qs[(dc + i + 3) * 64 + qq] = vv.w;
        }
    }

    float o[4][4];
    float m[4], l[4];
    #pragma unroll
    for (int i = 0; i < 4; i++) {
        m[i] = -1e30f; l[i] = 0.0f;
        #pragma unroll
        for (int j = 0; j < 4; j++) o[i][j] = 0.0f;
    }

    int ntiles = CAUSAL ? (qt + 1) : (S_LEN / 64);
    for (int kt = 0; kt < ntiles; kt++) {
        __syncthreads();
        {
            int kk = tid & 63;
            int dc = (tid >> 6) << 4;
            const float* ks = K + ((size_t)((b * S_LEN + kt * 64 + kk) * H_NUM + hh)) * D_DIM + dc;
            #pragma unroll
            for (int i = 0; i < 16; i += 4) {
                float4 vv = *(const float4*)(ks + i);
                KP[(dc + i + 0) * 64 + kk] = vv.x;
                KP[(dc + i + 1) * 64 + kk] = vv.y;
                KP[(dc + i + 2) * 64 + kk] = vv.z;
                KP[(dc + i + 3) * 64 + kk] = vv.w;
            }
            int kv = tid >> 2;
            int d4 = (tid & 3) << 4;
            const float* vsp = V + ((size_t)((b * S_LEN + kt * 64 + kv) * H_NUM + hh)) * D_DIM + d4;
            #pragma unroll
            for (int i = 0; i < 16; i += 4)
                *(float4*)&Vs[kv * 64 + d4 + i] = *(const float4*)(vsp + i);
        }
        __syncthreads();

        float s[4][4];
        #pragma unroll
        for (int i = 0; i < 4; i++)
            #pragma unroll
            for (int j = 0; j < 4; j++) s[i][j] = 0.0f;
        #pragma unroll 8
        for (int d = 0; d < 64; d++) {
            float4 a  = *(const float4*)&Qs[d * 64 + (qy << 2)];
            float4 bb = *(const float4*)&KP[d * 64 + (tx << 2)];
            float av[4] = {a.x, a.y, a.z, a.w};
            float bv[4] = {bb.x, bb.y, bb.z, bb.w};
            #pragma unroll
            for (int i = 0; i < 4; i++)
                #pragma unroll
                for (int j = 0; j < 4; j++)
                    s[i][j] += av[i] * bv[j];
        }

        if (CAUSAL && kt == qt) {
            #pragma unroll
            for (int i = 0; i < 4; i++)
                #pragma unroll
                for (int j = 0; j < 4; j++)
                    if ((tx << 2) + j > (qy << 2) + i) s[i][j] = -1e30f;
        }

        #pragma unroll
        for (int i = 0; i < 4; i++) {
            float mt = fmaxf(fmaxf(s[i][0], s[i][1]), fmaxf(s[i][2], s[i][3]));
            #pragma unroll
            for (int off = 1; off < 16; off <<= 1)
                mt = fmaxf(mt, __shfl_xor_sync(0xffffffffu, mt, off));
            float mn = fmaxf(m[i], mt);
            float sc = __expf(m[i] - mn);
            float ts = 0.0f;
            #pragma unroll
            for (int j = 0; j < 4; j++) {
                s[i][j] = __expf(s[i][j] - mn);
                ts += s[i][j];
            }
            #pragma unroll
            for (int off = 1; off < 16; off <<= 1)
                ts += __shfl_xor_sync(0xffffffffu, ts, off);
            l[i] = l[i] * sc + ts;
            m[i] = mn;
            #pragma unroll
            for (int j = 0; j < 4; j++) o[i][j] *= sc;
        }

        __syncthreads();
        #pragma unroll
        for (int kj = 0; kj < 4; kj++) {
            int kkk = (tx << 2) + kj;
            int col = ((qy ^ (kkk & 15)) << 2);
            *(float4*)&KP[kkk * 64 + col] = make_float4(s[0][kj], s[1][kj], s[2][kj], s[3][kj]);
        }
        __syncthreads();

        #pragma unroll 8
        for (int kkk = 0; kkk < 64; kkk++) {
            float4 a  = *(const float4*)&KP[kkk * 64 + ((qy ^ (kkk & 15)) << 2)];
            float4 bb = *(const float4*)&Vs[kkk * 64 + (tx << 2)];
            float av[4] = {a.x, a.y, a.z, a.w};
            float bv[4] = {bb.x, bb.y, bb.z, bb.w};
            #pragma unroll
            for (int i = 0; i < 4; i++)
                #pragma unroll
                for (int j = 0; j < 4; j++)
                    o[i][j] += av[i] * bv[j];
        }
    }

    #pragma unroll
    for (int i = 0; i < 4; i++) {
        float inv = 1.0f / l[i];
        int qq = qt * 64 + (qy << 2) + i;
        size_t idx = ((size_t)((b * S_LEN + qq) * H_NUM + hh)) * D_DIM + (tx << 2);
        float v0 = o[i][0] * inv, v1 = o[i][1] * inv;
        float v2 = o[i][2] * inv, v3 = o[i][3] * inv;
        __nv_bfloat16 h0, h1, h2, h3, l0, l1, l2, l3;
        bf_split(v0, h0, l0); bf_split(v1, h1, l1);
        bf_split(v2, h2, l2); bf_split(v3, h3, l3);
        __nv_bfloat162 a, bb;
        a.x = h0; a.y = h1; bb.x = h2; bb.y = h3;
        *(__nv_bfloat162*)(Oh + idx) = a; *(__nv_bfloat162*)(Oh + idx + 2) = bb;
        a.x = l0; a.y = l1; bb.x = l2; bb.y = l3;
        *(__nv_bfloat162*)(Ol + idx) = a; *(__nv_bfloat162*)(Ol + idx + 2) = bb;
    }
}

// ---------------- launch ------------------------------------------------------
extern "C" void kernel_launch(void* const* d_in, const int* in_sizes, int n_in,
                              void* d_out, int out_size) {
    const float* x    = (const float*)d_in[0];
    const float* enc  = (const float*)d_in[1];
    const float* ln1g = (const float*)d_in[2];
    const float* ln1b = (const float*)d_in[3];
    const float* ln2g = (const float*)d_in[4];
    const float* ln2b = (const float*)d_in[5];
    const float* ln3g = (const float*)d_in[6];
    const float* ln3b = (const float*)d_in[7];
    const float* Wq1  = (const float*)d_in[8];
    const float* bq1  = (const float*)d_in[9];
    const float* Wk1  = (const float*)d_in[10];
    const float* bk1  = (const float*)d_in[11];
    const float* Wv1  = (const float*)d_in[12];
    const float* bv1  = (const float*)d_in[13];
    const float* Wo1  = (const float*)d_in[14];
    const float* bo1  = (const float*)d_in[15];
    const float* Wq2  = (const float*)d_in[16];
    const float* bq2  = (const float*)d_in[17];
    const float* Wk2  = (const float*)d_in[18];
    const float* bk2  = (const float*)d_in[19];
    const float* Wv2  = (const float*)d_in[20];
    const float* bv2  = (const float*)d_in[21];
    const float* Wo2  = (const float*)d_in[22];
    const float* bo2  = (const float*)d_in[23];
    const float* Wup  = (const float*)d_in[24];
    const float* bup  = (const float*)d_in[25];
    const float* Wdn  = (const float*)d_in[26];
    const float* bdn  = (const float*)d_in[27];
    float* out = (float*)d_out;

    __nv_bfloat16 *Bh, *Bl, *hh, *hl, *ath, *atl, *ech, *ecl, *ffh, *ffl;
    float *q, *k, *v, *x1, *x2;
    cudaGetSymbolAddress((void**)&Bh,  g_Bh);
    cudaGetSymbolAddress((void**)&Bl,  g_Bl);
    cudaGetSymbolAddress((void**)&hh,  g_hh);
    cudaGetSymbolAddress((void**)&hl,  g_hl);
    cudaGetSymbolAddress((void**)&ath, g_ath);
    cudaGetSymbolAddress((void**)&atl, g_atl);
    cudaGetSymbolAddress((void**)&ech, g_ech);
    cudaGetSymbolAddress((void**)&ecl, g_ecl);
    cudaGetSymbolAddress((void**)&ffh, g_ffh);
    cudaGetSymbolAddress((void**)&ffl, g_ffl);
    cudaGetSymbolAddress((void**)&q,   g_q);
    cudaGetSymbolAddress((void**)&k,   g_k);
    cudaGetSymbolAddress((void**)&v,   g_v);
    cudaGetSymbolAddress((void**)&x1,  g_x1);
    cudaGetSymbolAddress((void**)&x2,  g_x2);

    cudaFuncSetAttribute(gemm_hmma<0>, cudaFuncAttributeMaxDynamicSharedMemorySize, GEMM_SMEM);
    cudaFuncSetAttribute(gemm_hmma<1>, cudaFuncAttributeMaxDynamicSharedMemorySize, GEMM_SMEM);
    cudaFuncSetAttribute(gemm_hmma<2>, cudaFuncAttributeMaxDynamicSharedMemorySize, GEMM_SMEM);

    // Weight prep: transpose + bf16 hi/lo split
    wqkv_split<<<4096, 256>>>(Wq1, Bh + 0 * MB1, Bl + 0 * MB1);
    wqkv_split<<<4096, 256>>>(Wk1, Bh + 1 * MB1, Bl + 1 * MB1);
    wqkv_split<<<4096, 256>>>(Wv1, Bh + 2 * MB1, Bl + 2 * MB1);
    wqkv_split<<<4096, 256>>>(Wq2, Bh + 3 * MB1, Bl + 3 * MB1);
    wqkv_split<<<4096, 256>>>(Wk2, Bh + 4 * MB1, Bl + 4 * MB1);
    wqkv_split<<<4096, 256>>>(Wv2, Bh + 5 * MB1, Bl + 5 * MB1);
    wt_split<<<dim3(32, 32),  dim3(32, 8)>>>(Wo1, Bh + 6 * MB1,  Bl + 6 * MB1,  1024, 1024);
    wt_split<<<dim3(32, 32),  dim3(32, 8)>>>(Wo2, Bh + 7 * MB1,  Bl + 7 * MB1,  1024, 1024);
    wt_split<<<dim3(128, 32), dim3(32, 8)>>>(Wup, Bh + 8 * MB1,  Bl + 8 * MB1,  1024, 4096);
    wt_split<<<dim3(32, 128), dim3(32, 8)>>>(Wdn, Bh + 12 * MB1, Bl + 12 * MB1, 4096, 1024);
    split4<<<4096, 256>>>(enc, ech, ecl);

    dim3 gSq(8, 32);       // N=1024
    dim3 gUp(32, 32);      // N=4096
    dim3 gAttn(S_LEN / 64, H_NUM, B_NUM);

    // Block 1: causal self-attention
    ln_kernel<<<M_ROWS, 256>>>(x, ln1g, ln1b, hh, hl);
    gemm_hmma<0><<<gSq, 128, GEMM_SMEM>>>(hh, hl, Bh + 0 * MB1, Bl + 0 * MB1, bq1, nullptr, q, nullptr, nullptr, M_ROWS, E_DIM, E_DIM);
    gemm_hmma<0><<<gSq, 128, GEMM_SMEM>>>(hh, hl, Bh + 1 * MB1, Bl + 1 * MB1, bk1, nullptr, k, nullptr, nullptr, M_ROWS, E_DIM, E_DIM);
    gemm_hmma<0><<<gSq, 128, GEMM_SMEM>>>(hh, hl, Bh + 2 * MB1, Bl + 2 * MB1, bv1, nullptr, v, nullptr, nullptr, M_ROWS, E_DIM, E_DIM);
    attn_kernel<true><<<gAttn, 256>>>(q, k, v, ath, atl);
    gemm_hmma<2><<<gSq, 128, GEMM_SMEM>>>(ath, atl, Bh + 6 * MB1, Bl + 6 * MB1, bo1, x, x1, nullptr, nullptr, M_ROWS, E_DIM, E_DIM);

    // Block 2: cross-attention
    ln_kernel<<<M_ROWS, 256>>>(x1, ln2g, ln2b, hh, hl);
    gemm_hmma<0><<<gSq, 128, GEMM_SMEM>>>(hh, hl,   Bh + 3 * MB1, Bl + 3 * MB1, bq2, nullptr, q, nullptr, nullptr, M_ROWS, E_DIM, E_DIM);
    gemm_hmma<0><<<gSq, 128, GEMM_SMEM>>>(ech, ecl, Bh + 4 * MB1, Bl + 4 * MB1, bk2, nullptr, k, nullptr, nullptr, M_ROWS, E_DIM, E_DIM);
    gemm_hmma<0><<<gSq, 128, GEMM_SMEM>>>(ech, ecl, Bh + 5 * MB1, Bl + 5 * MB1, bv2, nullptr, v, nullptr, nullptr, M_ROWS, E_DIM, E_DIM);
    attn_kernel<false><<<gAttn, 256>>>(q, k, v, ath, atl);
    gemm_hmma<2><<<gSq, 128, GEMM_SMEM>>>(ath, atl, Bh + 7 * MB1, Bl + 7 * MB1, bo2, x1, x2, nullptr, nullptr, M_ROWS, E_DIM, E_DIM);

    // FFN
    ln_kernel<<<M_ROWS, 256>>>(x2, ln3g, ln3b, hh, hl);
    gemm_hmma<1><<<gUp, 128, GEMM_SMEM>>>(hh, hl, Bh + 8 * MB1, Bl + 8 * MB1, bup, nullptr, nullptr, ffh, ffl, M_ROWS, F_DIM, E_DIM);
    gemm_hmma<2><<<gSq, 128, GEMM_SMEM>>>(ffh, ffl, Bh + 12 * MB1, Bl + 12 * MB1, bdn, x2, out, nullptr, nullptr, M_ROWS, E_DIM, F_DIM);
}

// round 4
// speedup vs baseline: 2.6855x; 1.4325x over previous
#include <cuda_runtime.h>
#include <cuda_bf16.h>
#include <math.h>
#include <cstdint>

#define E_DIM 1024
#define H_NUM 16
#define D_DIM 64
#define B_NUM 4
#define S_LEN 1024
#define F_DIM 4096
#define M_ROWS (B_NUM * S_LEN)  // 4096
#define MB1 (1024 * 1024)

// ---------------- scratch (static device globals) ---------------------------
__device__ __align__(16) __nv_bfloat16 g_Bh[16 * MB1];
__device__ __align__(16) __nv_bfloat16 g_Bl[16 * MB1];
__device__ __align__(16) __nv_bfloat16 g_hh[4 * MB1], g_hl[4 * MB1];
__device__ __align__(16) __nv_bfloat16 g_ath[4 * MB1], g_atl[4 * MB1];
__device__ __align__(16) __nv_bfloat16 g_ech[4 * MB1], g_ecl[4 * MB1];
__device__ __align__(16) __nv_bfloat16 g_ffh[16 * MB1], g_ffl[16 * MB1];
__device__ __align__(16) __nv_bfloat16 g_qh[4 * MB1], g_ql[4 * MB1];
__device__ __align__(16) __nv_bfloat16 g_kh[4 * MB1], g_kl[4 * MB1];
__device__ __align__(16) __nv_bfloat16 g_vh[4 * MB1], g_vl[4 * MB1];
__device__ __align__(16) float g_x1[4 * MB1], g_x2[4 * MB1];

// ---------------- PTX helpers -----------------------------------------------
__device__ __forceinline__ uint32_t smem_u32(const void* p) {
    uint32_t a;
    asm("{ .reg .u64 t; cvta.to.shared.u64 t, %1; cvt.u32.u64 %0, t; }" : "=r"(a) : "l"(p));
    return a;
}
__device__ __forceinline__ void cpasync16(uint32_t dst, const void* src) {
    asm volatile("cp.async.cg.shared.global [%0], [%1], 16;" :: "r"(dst), "l"(src));
}
__device__ __forceinline__ void cpcommit() { asm volatile("cp.async.commit_group;" ::: "memory"); }
template <int N>
__device__ __forceinline__ void cpwait() { asm volatile("cp.async.wait_group %0;" :: "n"(N) : "memory"); }

__device__ __forceinline__ void ldsm4(uint32_t (&r)[4], uint32_t addr) {
    asm volatile("ldmatrix.sync.aligned.m8n8.x4.shared.b16 {%0,%1,%2,%3}, [%4];"
                 : "=r"(r[0]), "=r"(r[1]), "=r"(r[2]), "=r"(r[3]) : "r"(addr));
}
__device__ __forceinline__ void ldsm4t(uint32_t (&r)[4], uint32_t addr) {
    asm volatile("ldmatrix.sync.aligned.m8n8.x4.trans.shared.b16 {%0,%1,%2,%3}, [%4];"
                 : "=r"(r[0]), "=r"(r[1]), "=r"(r[2]), "=r"(r[3]) : "r"(addr));
}
__device__ __forceinline__ void ldsm2(uint32_t (&r)[2], uint32_t addr) {
    asm volatile("ldmatrix.sync.aligned.m8n8.x2.shared.b16 {%0,%1}, [%2];"
                 : "=r"(r[0]), "=r"(r[1]) : "r"(addr));
}
__device__ __forceinline__ void mma16816(float (&d)[4], const uint32_t (&a)[4],
                                         const uint32_t (&b)[2]) {
    asm volatile(
        "mma.sync.aligned.m16n8k16.row.col.f32.bf16.bf16.f32 "
        "{%0,%1,%2,%3}, {%4,%5,%6,%7}, {%8,%9}, {%0,%1,%2,%3};"
        : "+f"(d[0]), "+f"(d[1]), "+f"(d[2]), "+f"(d[3])
        : "r"(a[0]), "r"(a[1]), "r"(a[2]), "r"(a[3]), "r"(b[0]), "r"(b[1]));
}
__device__ __forceinline__ uint32_t swz128(uint32_t o) { return o ^ ((o >> 3) & 0x70); }

__device__ __forceinline__ void bf_split(float v, __nv_bfloat16& hi, __nv_bfloat16& lo) {
    hi = __float2bfloat16_rn(v);
    lo = __float2bfloat16_rn(v - __bfloat162float(hi));
}
__device__ __forceinline__ void packsplit(float a, float b, uint32_t& hi, uint32_t& lo) {
    __nv_bfloat16 ah, al, bh, bl;
    bf_split(a, ah, al); bf_split(b, bh, bl);
    __nv_bfloat162 hp, lp;
    hp.x = ah; hp.y = bh; lp.x = al; lp.y = bl;
    hi = *(uint32_t*)&hp; lo = *(uint32_t*)&lp;
}

// ---------------- weight prep kernels ---------------------------------------
__global__ void wqkv_split(const float* __restrict__ src,
                           __nv_bfloat16* __restrict__ oh, __nv_bfloat16* __restrict__ ol) {
    int idx = blockIdx.x * 256 + threadIdx.x;
    int n = idx >> 10, k = idx & 1023;
    int h = n >> 6, d = n & 63;
    float v = src[h * (E_DIM * D_DIM) + k * D_DIM + d];
    __nv_bfloat16 hi, lo; bf_split(v, hi, lo);
    oh[idx] = hi; ol[idx] = lo;
}
__global__ void wt_split(const float* __restrict__ src,
                         __nv_bfloat16* __restrict__ oh, __nv_bfloat16* __restrict__ ol,
                         int K, int N) {
    __shared__ float tile[32][33];
    int n0 = blockIdx.x * 32, k0 = blockIdx.y * 32;
    int tx = threadIdx.x, ty = threadIdx.y;
    #pragma unroll
    for (int i = 0; i < 4; i++)
        tile[ty + 8 * i][tx] = src[(size_t)(k0 + ty + 8 * i) * N + n0 + tx];
    __syncthreads();
    #pragma unroll
    for (int i = 0; i < 4; i++) {
        float v = tile[tx][ty + 8 * i];
        __nv_bfloat16 hi, lo; bf_split(v, hi, lo);
        size_t oidx = (size_t)(n0 + ty + 8 * i) * K + k0 + tx;
        oh[oidx] = hi; ol[oidx] = lo;
    }
}
__global__ void split4(const float* __restrict__ src,
                       __nv_bfloat16* __restrict__ oh, __nv_bfloat16* __restrict__ ol) {
    int i = blockIdx.x * 256 + threadIdx.x;
    float4 v = ((const float4*)src)[i];
    uint32_t h0, h1, l0, l1;
    packsplit(v.x, v.y, h0, l0);
    packsplit(v.z, v.w, h1, l1);
    *(uint32_t*)(oh + 4 * (size_t)i) = h0;
    *(uint32_t*)(oh + 4 * (size_t)i + 2) = h1;
    *(uint32_t*)(ol + 4 * (size_t)i) = l0;
    *(uint32_t*)(ol + 4 * (size_t)i + 2) = l1;
}

// ---------------- LayerNorm: f32 in -> bf16 hi/lo out ------------------------
__global__ void __launch_bounds__(256) ln_kernel(const float* __restrict__ x,
                                                 const float* __restrict__ g,
                                                 const float* __restrict__ b,
                                                 __nv_bfloat16* __restrict__ oh,
                                                 __nv_bfloat16* __restrict__ ol) {
    int row = blockIdx.x;
    int t = threadIdx.x;
    float4 v = ((const float4*)(x + (size_t)row * E_DIM))[t];
    float s = v.x + v.y + v.z + v.w;
    float ss = v.x * v.x + v.y * v.y + v.z * v.z + v.w * v.w;
    #pragma unroll
    for (int o = 16; o > 0; o >>= 1) {
        s  += __shfl_xor_sync(0xffffffffu, s, o);
        ss += __shfl_xor_sync(0xffffffffu, ss, o);
    }
    __shared__ float red[2][8];
    int w = t >> 5, lane = t & 31;
    if (lane == 0) { red[0][w] = s; red[1][w] = ss; }
    __syncthreads();
    s = 0.0f; ss = 0.0f;
    #pragma unroll
    for (int i = 0; i < 8; i++) { s += red[0][i]; ss += red[1][i]; }
    float mu  = s * (1.0f / E_DIM);
    float var = ss * (1.0f / E_DIM) - mu * mu;
    float inv = rsqrtf(var + 1e-5f);
    float4 gv = ((const float4*)g)[t];
    float4 bv = ((const float4*)b)[t];
    float o0 = (v.x - mu) * inv * gv.x + bv.x;
    float o1 = (v.y - mu) * inv * gv.y + bv.y;
    float o2 = (v.z - mu) * inv * gv.z + bv.z;
    float o3 = (v.w - mu) * inv * gv.w + bv.w;
    uint32_t h0, h1, l0, l1;
    packsplit(o0, o1, h0, l0);
    packsplit(o2, o3, h1, l1);
    size_t base = (size_t)row * E_DIM + t * 4;
    *(uint32_t*)(oh + base) = h0; *(uint32_t*)(oh + base + 2) = h1;
    *(uint32_t*)(ol + base) = l0; *(uint32_t*)(ol + base + 2) = l1;
}

// ---------------- HMMA bf16x3 GEMM -------------------------------------------
// EPI: 0 bias->f32, 1 bias+GELU->bf16 hi/lo, 2 bias+res->f32, 3 bias->bf16 hi/lo
#define STAGE_BYTES 32768
#define GEMM_SMEM (2 * STAGE_BYTES + 256)
template <int EPI>
__global__ void __launch_bounds__(128, 2) gemm_hmma(
    const __nv_bfloat16* __restrict__ Ah, const __nv_bfloat16* __restrict__ Al,
    const __nv_bfloat16* __restrict__ Bh, const __nv_bfloat16* __restrict__ Bl,
    const float* __restrict__ bias, const float* __restrict__ res,
    float* __restrict__ outF, __nv_bfloat16* __restrict__ outH, __nv_bfloat16* __restrict__ outL,
    int M, int N, int K) {
    extern __shared__ char dyn[];
    uint32_t sb = (smem_u32(dyn) + 127) & ~127u;
    int tid = threadIdx.x, lane = tid & 31, wid = tid >> 5;
    int rBase = blockIdx.y * 128, cBase = blockIdx.x * 128;
    int m0 = (wid >> 1) * 64, n0 = (wid & 1) * 64;

    float acc[4][8][4];
    #pragma unroll
    for (int i = 0; i < 4; i++)
        #pragma unroll
        for (int j = 0; j < 8; j++)
            #pragma unroll
            for (int u = 0; u < 4; u++) acc[i][j][u] = 0.0f;

    const int nc = K >> 5;
    auto loadStage = [&](int s, int c) {
        uint32_t base = sb + s * STAGE_BYTES;
        int k0 = c << 5;
        #pragma unroll
        for (int i = 0; i < 4; i++) {
            int idx = i * 128 + tid;
            int row = idx >> 2, seg = idx & 3;
            uint32_t off = (seg >> 1) * 4096 + (((row * 32) + (seg & 1) * 16) ^ ((row & 4) << 2));
            size_t ga = (size_t)(rBase + row) * K + k0 + seg * 8;
            size_t gb = (size_t)(cBase + row) * K + k0 + seg * 8;
            cpasync16(base + off,         Ah + ga);
            cpasync16(base + 8192 + off,  Al + ga);
            cpasync16(base + 16384 + off, Bh + gb);
            cpasync16(base + 24576 + off, Bl + gb);
        }
    };

    int aRow = (lane & 7) + ((lane >> 3) & 1) * 8;
    int aH   = lane >> 4;
    int bRow = lane & 7;
    int bH   = (lane >> 3) & 1;

    loadStage(0, 0); cpcommit();

    for (int c = 0; c < nc; c++) {
        if (c + 1 < nc) { loadStage((c + 1) & 1, c + 1); cpcommit(); cpwait<1>(); }
        else            { cpwait<0>(); }
        __syncthreads();
        uint32_t base = sb + (c & 1) * STAGE_BYTES;
        #pragma unroll
        for (int kc = 0; kc < 2; kc++) {
            uint32_t bh[8][2], bl[8][2];
            #pragma unroll
            for (int j = 0; j < 8; j++) {
                int row = n0 + j * 8 + bRow;
                uint32_t off = kc * 4096 + (((row * 32) + bH * 16) ^ ((row & 4) << 2));
                ldsm2(bh[j], base + 16384 + off);
                ldsm2(bl[j], base + 24576 + off);
            }
            #pragma unroll
            for (int i = 0; i < 4; i++) {
                uint32_t ah[4], al[4];
                int row = m0 + i * 16 + aRow;
                uint32_t off = kc * 4096 + (((row * 32) + aH * 16) ^ ((row & 4) << 2));
                ldsm4(ah, base + off);
                ldsm4(al, base + 8192 + off);
                #pragma unroll
                for (int j = 0; j < 8; j++) {
                    mma16816(acc[i][j], ah, bh[j]);
                    mma16816(acc[i][j], ah, bl[j]);
                    mma16816(acc[i][j], al, bh[j]);
                }
            }
        }
        __syncthreads();
    }

    int lr = lane >> 2, lc = (lane & 3) << 1;
    #pragma unroll
    for (int i = 0; i < 4; i++) {
        #pragma unroll
        for (int half = 0; half < 2; half++) {
            size_t row = (size_t)(rBase + m0 + i * 16 + lr + half * 8);
            #pragma unroll
            for (int j = 0; j < 8; j++) {
                int col = cBase + n0 + j * 8 + lc;
                float v0 = acc[i][j][half * 2 + 0] + bias[col];
                float v1 = acc[i][j][half * 2 + 1] + bias[col + 1];
                if (EPI == 1 || EPI == 3) {
                    if (EPI == 1) {
                        v0 = 0.5f * v0 * (1.0f + erff(v0 * 0.70710678118654752f));
                        v1 = 0.5f * v1 * (1.0f + erff(v1 * 0.70710678118654752f));
                    }
                    uint32_t hp, lp;
                    packsplit(v0, v1, hp, lp);
                    *(uint32_t*)(outH + row * N + col) = hp;
                    *(uint32_t*)(outL + row * N + col) = lp;
                } else {
                    if (EPI == 2) {
                        float2 rv = *(const float2*)(res + row * N + col);
                        v0 += rv.x; v1 += rv.y;
                    }
                    float2 o; o.x = v0; o.y = v1;
                    *(float2*)(outF + row * N + col) = o;
                }
            }
        }
    }
}

// ---------------- HMMA flash attention (bf16x3, D=64) ------------------------
// grid (S/64, H, B), 128 threads (4 warps x 16 q-rows). Q/K/V: bf16 hi/lo,
// layout [token][h*64+d] (token-major, stride E_DIM). Double-buffered K/V.
// SMEM: Qh 0, Ql 8K | buf s at 16K+32K*s: Kh, Kl, Vh, Vl (8K each).
#define ATTN_SMEM (16384 + 2 * 32768 + 1024)
template <bool CAUSAL>
__global__ void __launch_bounds__(128, 2) attn_hmma(
    const __nv_bfloat16* __restrict__ Qh, const __nv_bfloat16* __restrict__ Ql,
    const __nv_bfloat16* __restrict__ Kh, const __nv_bfloat16* __restrict__ Kl,
    const __nv_bfloat16* __restrict__ Vh, const __nv_bfloat16* __restrict__ Vl,
    __nv_bfloat16* __restrict__ Oh, __nv_bfloat16* __restrict__ Ol) {
    extern __shared__ char dyn[];
    uint32_t sb = (smem_u32(dyn) + 1023) & ~1023u;
    int tid = threadIdx.x, lane = tid & 31, w = tid >> 5;
    int b = blockIdx.z, hh = blockIdx.y, qt = blockIdx.x;
    size_t headOff = (size_t)hh * D_DIM;
    size_t tokBase = (size_t)b * S_LEN;

    int aRow = (lane & 7) + ((lane >> 3) & 1) * 8;
    int aC = lane >> 4;

    // Load Q tile (rows qt*64 .. +63)
    {
        #pragma unroll
        for (int i = 0; i < 4; i++) {
            int idx = i * 128 + tid;
            int r = idx >> 3, c = idx & 7;
            uint32_t off = swz128(r * 128 + c * 16);
            size_t src = (tokBase + qt * 64 + r) * E_DIM + headOff + c * 8;
            cpasync16(sb + off, Qh + src);
            cpasync16(sb + 8192 + off, Ql + src);
        }
    }
    auto loadKV = [&](int s, int kt) {
        uint32_t base = sb + 16384 + s * 32768;
        #pragma unroll
        for (int i = 0; i < 4; i++) {
            int idx = i * 128 + tid;
            int r = idx >> 3, c = idx & 7;
            uint32_t off = swz128(r * 128 + c * 16);
            size_t src = (tokBase + kt * 64 + r) * E_DIM + headOff + c * 8;
            cpasync16(base + off,         Kh + src);
            cpasync16(base + 8192 + off,  Kl + src);
            cpasync16(base + 16384 + off, Vh + src);
            cpasync16(base + 24576 + off, Vl + src);
        }
    };
    loadKV(0, 0);
    cpcommit();

    uint32_t qh[4][4], ql[4][4];
    float oacc[8][4];
    float mrow[2] = {-1e30f, -1e30f}, lrow[2] = {0.0f, 0.0f};
    #pragma unroll
    for (int j = 0; j < 8; j++)
        #pragma unroll
        for (int u = 0; u < 4; u++) oacc[j][u] = 0.0f;

    const int ntiles = CAUSAL ? (qt + 1) : (S_LEN / 64);
    for (int kt = 0; kt < ntiles; kt++) {
        if (kt + 1 < ntiles) { loadKV((kt + 1) & 1, kt + 1); cpcommit(); cpwait<1>(); }
        else                 { cpwait<0>(); }
        __syncthreads();
        if (kt == 0) {
            #pragma unroll
            for (int s = 0; s < 4; s++) {
                uint32_t addr = sb + swz128((w * 16 + aRow) * 128 + s * 32 + aC * 16);
                ldsm4(qh[s], addr);
                ldsm4(ql[s], addr + 8192);
            }
        }
        uint32_t kb = sb + 16384 + (kt & 1) * 32768;
        uint32_t vb = kb + 16384;

        // ---- scores: S = Q K^T (bf16x3) ----
        float sacc[8][4];
        #pragma unroll
        for (int j = 0; j < 8; j++)
            #pragma unroll
            for (int u = 0; u < 4; u++) sacc[j][u] = 0.0f;
        #pragma unroll
        for (int s = 0; s < 4; s++) {
            #pragma unroll
            for (int jp = 0; jp < 4; jp++) {
                uint32_t addr = kb + swz128((jp * 16 + aRow) * 128 + s * 32 + aC * 16);
                uint32_t kh4[4], kl4[4];
                ldsm4(kh4, addr);
                ldsm4(kl4, addr + 8192);
                uint32_t b0h[2] = {kh4[0], kh4[2]}, b1h[2] = {kh4[1], kh4[3]};
                uint32_t b0l[2] = {kl4[0], kl4[2]}, b1l[2] = {kl4[1], kl4[3]};
                mma16816(sacc[2 * jp],     qh[s], b0h);
                mma16816(sacc[2 * jp],     ql[s], b0h);
                mma16816(sacc[2 * jp],     qh[s], b0l);
                mma16816(sacc[2 * jp + 1], qh[s], b1h);
                mma16816(sacc[2 * jp + 1], ql[s], b1h);
                mma16816(sacc[2 * jp + 1], qh[s], b1l);
            }
        }

        if (CAUSAL && kt == qt) {
            int ql0 = w * 16 + (lane >> 2);
            #pragma unroll
            for (int j = 0; j < 8; j++)
                #pragma unroll
                for (int u = 0; u < 4; u++) {
                    int kcol = j * 8 + ((lane & 3) << 1) + (u & 1);
                    int qrow = ql0 + (u >> 1) * 8;
                    if (kcol > qrow) sacc[j][u] = -1e30f;
                }
        }

        // ---- online softmax ----
        #pragma unroll
        for (int h2 = 0; h2 < 2; h2++) {
            float mt = -1e30f;
            #pragma unroll
            for (int j = 0; j < 8; j++)
                mt = fmaxf(mt, fmaxf(sacc[j][2 * h2], sacc[j][2 * h2 + 1]));
            mt = fmaxf(mt, __shfl_xor_sync(0xffffffffu, mt, 1));
            mt = fmaxf(mt, __shfl_xor_sync(0xffffffffu, mt, 2));
            float mn = fmaxf(mrow[h2], mt);
            float sc = __expf(mrow[h2] - mn);
            mrow[h2] = mn;
            float ts = 0.0f;
            #pragma unroll
            for (int j = 0; j < 8; j++) {
                sacc[j][2 * h2]     = __expf(sacc[j][2 * h2] - mn);
                sacc[j][2 * h2 + 1] = __expf(sacc[j][2 * h2 + 1] - mn);
                ts += sacc[j][2 * h2] + sacc[j][2 * h2 + 1];
            }
            ts += __shfl_xor_sync(0xffffffffu, ts, 1);
            ts += __shfl_xor_sync(0xffffffffu, ts, 2);
            lrow[h2] = lrow[h2] * sc + ts;
            #pragma unroll
            for (int j = 0; j < 8; j++) {
                oacc[j][2 * h2]     *= sc;
                oacc[j][2 * h2 + 1] *= sc;
            }
        }

        // ---- O += P V (bf16x3) ----
        #pragma unroll
        for (int s = 0; s < 4; s++) {
            uint32_t ph4[4], pl4[4];
            packsplit(sacc[2 * s][0],     sacc[2 * s][1],     ph4[0], pl4[0]);
            packsplit(sacc[2 * s][2],     sacc[2 * s][3],     ph4[1], pl4[1]);
            packsplit(sacc[2 * s + 1][0], sacc[2 * s + 1][1], ph4[2], pl4[2]);
            packsplit(sacc[2 * s + 1][2], sacc[2 * s + 1][3], ph4[3], pl4[3]);
            #pragma unroll
            for (int jp = 0; jp < 4; jp++) {
                uint32_t addr = vb + swz128((s * 16 + aRow) * 128 + jp * 32 + aC * 16);
                uint32_t vh4[4], vl4[4];
                ldsm4t(vh4, addr);
                ldsm4t(vl4, addr + 8192);
                uint32_t b0h[2] = {vh4[0], vh4[1]}, b1h[2] = {vh4[2], vh4[3]};
                uint32_t b0l[2] = {vl4[0], vl4[1]}, b1l[2] = {vl4[2], vl4[3]};
                mma16816(oacc[2 * jp],     ph4, b0h);
                mma16816(oacc[2 * jp],     pl4, b0h);
                mma16816(oacc[2 * jp],     ph4, b0l);
                mma16816(oacc[2 * jp + 1], ph4, b1h);
                mma16816(oacc[2 * jp + 1], pl4, b1h);
                mma16816(oacc[2 * jp + 1], ph4, b1l);
            }
        }
        __syncthreads();
    }

    // ---- epilogue: O / l -> bf16 hi/lo ----
    #pragma unroll
    for (int h2 = 0; h2 < 2; h2++) {
        float inv = 1.0f / lrow[h2];
        int trow = qt * 64 + w * 16 + (lane >> 2) + h2 * 8;
        size_t rp = (tokBase + trow) * E_DIM + headOff;
        #pragma unroll
        for (int j = 0; j < 8; j++) {
            float v0 = oacc[j][2 * h2] * inv;
            float v1 = oacc[j][2 * h2 + 1] * inv;
            uint32_t hp, lp;
            packsplit(v0, v1, hp, lp);
            int col = j * 8 + ((lane & 3) << 1);
            *(uint32_t*)(Oh + rp + col) = hp;
            *(uint32_t*)(Ol + rp + col) = lp;
        }
    }
}

// ---------------- launch ------------------------------------------------------
extern "C" void kernel_launch(void* const* d_in, const int* in_sizes, int n_in,
                              void* d_out, int out_size) {
    const float* x    = (const float*)d_in[0];
    const float* enc  = (const float*)d_in[1];
    const float* ln1g = (const float*)d_in[2];
    const float* ln1b = (const float*)d_in[3];
    const float* ln2g = (const float*)d_in[4];
    const float* ln2b = (const float*)d_in[5];
    const float* ln3g = (const float*)d_in[6];
    const float* ln3b = (const float*)d_in[7];
    const float* Wq1  = (const float*)d_in[8];
    const float* bq1  = (const float*)d_in[9];
    const float* Wk1  = (const float*)d_in[10];
    const float* bk1  = (const float*)d_in[11];
    const float* Wv1  = (const float*)d_in[12];
    const float* bv1  = (const float*)d_in[13];
    const float* Wo1  = (const float*)d_in[14];
    const float* bo1  = (const float*)d_in[15];
    const float* Wq2  = (const float*)d_in[16];
    const float* bq2  = (const float*)d_in[17];
    const float* Wk2  = (const float*)d_in[18];
    const float* bk2  = (const float*)d_in[19];
    const float* Wv2  = (const float*)d_in[20];
    const float* bv2  = (const float*)d_in[21];
    const float* Wo2  = (const float*)d_in[22];
    const float* bo2  = (const float*)d_in[23];
    const float* Wup  = (const float*)d_in[24];
    const float* bup  = (const float*)d_in[25];
    const float* Wdn  = (const float*)d_in[26];
    const float* bdn  = (const float*)d_in[27];
    float* out = (float*)d_out;

    __nv_bfloat16 *Bh, *Bl, *hh, *hl, *ath, *atl, *ech, *ecl, *ffh, *ffl;
    __nv_bfloat16 *qh, *ql, *kh, *kl, *vh, *vl;
    float *x1, *x2;
    cudaGetSymbolAddress((void**)&Bh,  g_Bh);
    cudaGetSymbolAddress((void**)&Bl,  g_Bl);
    cudaGetSymbolAddress((void**)&hh,  g_hh);
    cudaGetSymbolAddress((void**)&hl,  g_hl);
    cudaGetSymbolAddress((void**)&ath, g_ath);
    cudaGetSymbolAddress((void**)&atl, g_atl);
    cudaGetSymbolAddress((void**)&ech, g_ech);
    cudaGetSymbolAddress((void**)&ecl, g_ecl);
    cudaGetSymbolAddress((void**)&ffh, g_ffh);
    cudaGetSymbolAddress((void**)&ffl, g_ffl);
    cudaGetSymbolAddress((void**)&qh,  g_qh);
    cudaGetSymbolAddress((void**)&ql,  g_ql);
    cudaGetSymbolAddress((void**)&kh,  g_kh);
    cudaGetSymbolAddress((void**)&kl,  g_kl);
    cudaGetSymbolAddress((void**)&vh,  g_vh);
    cudaGetSymbolAddress((void**)&vl,  g_vl);
    cudaGetSymbolAddress((void**)&x1,  g_x1);
    cudaGetSymbolAddress((void**)&x2,  g_x2);

    cudaFuncSetAttribute(gemm_hmma<1>, cudaFuncAttributeMaxDynamicSharedMemorySize, GEMM_SMEM);
    cudaFuncSetAttribute(gemm_hmma<2>, cudaFuncAttributeMaxDynamicSharedMemorySize, GEMM_SMEM);
    cudaFuncSetAttribute(gemm_hmma<3>, cudaFuncAttributeMaxDynamicSharedMemorySize, GEMM_SMEM);
    cudaFuncSetAttribute(attn_hmma<true>,  cudaFuncAttributeMaxDynamicSharedMemorySize, ATTN_SMEM);
    cudaFuncSetAttribute(attn_hmma<false>, cudaFuncAttributeMaxDynamicSharedMemorySize, ATTN_SMEM);

    const int WS = E_DIM * E_DIM;  // 1M elements per square weight slot
    dim3 gSq(8, 32);
    dim3 gUp(32, 32);
    dim3 gAttn(S_LEN / 64, H_NUM, B_NUM);

    // Launch order arranged so ncu (-s 5 -c 1) captures a GEMM (launch idx 5).
    wqkv_split<<<4096, 256>>>(Wq1, Bh + 0 * WS, Bl + 0 * WS);                              // 0
    wqkv_split<<<4096, 256>>>(Wk1, Bh + 1 * WS, Bl + 1 * WS);                              // 1
    wqkv_split<<<4096, 256>>>(Wv1, Bh + 2 * WS, Bl + 2 * WS);                              // 2
    split4<<<4096, 256>>>(enc, ech, ecl);                                                  // 3
    ln_kernel<<<M_ROWS, 256>>>(x, ln1g, ln1b, hh, hl);                                     // 4
    gemm_hmma<3><<<gSq, 128, GEMM_SMEM>>>(hh, hl, Bh + 0 * WS, Bl + 0 * WS, bq1, nullptr,
                                          nullptr, qh, ql, M_ROWS, E_DIM, E_DIM);          // 5 (ncu)
    gemm_hmma<3><<<gSq, 128, GEMM_SMEM>>>(hh, hl, Bh + 1 * WS, Bl + 1 * WS, bk1, nullptr,
                                          nullptr, kh, kl, M_ROWS, E_DIM, E_DIM);          // 6
    gemm_hmma<3><<<gSq, 128, GEMM_SMEM>>>(hh, hl, Bh + 2 * WS, Bl + 2 * WS, bv1, nullptr,
                                          nullptr, vh, vl, M_ROWS, E_DIM, E_DIM);          // 7
    attn_hmma<true><<<gAttn, 128, ATTN_SMEM>>>(qh, ql, kh, kl, vh, vl, ath, atl);          // 8
    wt_split<<<dim3(32, 32), dim3(32, 8)>>>(Wo1, Bh + 6 * WS, Bl + 6 * WS, 1024, 1024);    // 9
    gemm_hmma<2><<<gSq, 128, GEMM_SMEM>>>(ath, atl, Bh + 6 * WS, Bl + 6 * WS, bo1, x,
                                          x1, nullptr, nullptr, M_ROWS, E_DIM, E_DIM);     // 10

    ln_kernel<<<M_ROWS, 256>>>(x1, ln2g, ln2b, hh, hl);                                    // 11
    wqkv_split<<<4096, 256>>>(Wq2, Bh + 3 * WS, Bl + 3 * WS);                              // 12
    wqkv_split<<<4096, 256>>>(Wk2, Bh + 4 * WS, Bl + 4 * WS);                              // 13
    wqkv_split<<<4096, 256>>>(Wv2, Bh + 5 * WS, Bl + 5 * WS);                              // 14
    gemm_hmma<3><<<gSq, 128, GEMM_SMEM>>>(hh, hl,   Bh + 3 * WS, Bl + 3 * WS, bq2, nullptr,
                                          nullptr, qh, ql, M_ROWS, E_DIM, E_DIM);          // 15
    gemm_hmma<3><<<gSq, 128, GEMM_SMEM>>>(ech, ecl, Bh + 4 * WS, Bl + 4 * WS, bk2, nullptr,
                                          nullptr, kh, kl, M_ROWS, E_DIM, E_DIM);          // 16
    gemm_hmma<3><<<gSq, 128, GEMM_SMEM>>>(ech, ecl, Bh + 5 * WS, Bl + 5 * WS, bv2, nullptr,
                                          nullptr, vh, vl, M_ROWS, E_DIM, E_DIM);          // 17
    attn_hmma<false><<<gAttn, 128, ATTN_SMEM>>>(qh, ql, kh, kl, vh, vl, ath, atl);         // 18
    wt_split<<<dim3(32, 32), dim3(32, 8)>>>(Wo2, Bh + 7 * WS, Bl + 7 * WS, 1024, 1024);    // 19
    gemm_hmma<2><<<gSq, 128, GEMM_SMEM>>>(ath, atl, Bh + 7 * WS, Bl + 7 * WS, bo2, x1,
                                          x2, nullptr, nullptr, M_ROWS, E_DIM, E_DIM);     // 20

    ln_kernel<<<M_ROWS, 256>>>(x2, ln3g, ln3b, hh, hl);                                    // 21
    wt_split<<<dim3(128, 32), dim3(32, 8)>>>(Wup, Bh + 8 * WS, Bl + 8 * WS, 1024, 4096);   // 22
    gemm_hmma<1><<<gUp, 128, GEMM_SMEM>>>(hh, hl, Bh + 8 * WS, Bl + 8 * WS, bup, nullptr,
                                          nullptr, ffh, ffl, M_ROWS, F_DIM, E_DIM);        // 23
    wt_split<<<dim3(32, 128), dim3(32, 8)>>>(Wdn, Bh + 12 * WS, Bl + 12 * WS, 4096, 1024); // 24
    gemm_hmma<2><<<gSq, 128, GEMM_SMEM>>>(ffh, ffl, Bh + 12 * WS, Bl + 12 * WS, bdn, x2,
                                          out, nullptr, nullptr, M_ROWS, E_DIM, F_DIM);    // 25
}